// round 1
// baseline (speedup 1.0000x reference)
#include <cuda_runtime.h>
#include <cuda_bf16.h>

// VQLayer forward: quantized = closest + stop_gradient(inputs - closest)
//                            = inputs   (exact algebraic identity in the forward value;
//                                        stop_gradient only affects autodiff)
// The distance/argmin/gather pipeline contributes nothing to the forward output.
// Therefore the optimal kernel is a bandwidth-bound copy of inputs -> out.
// 8 MB in + 8 MB out => ~2.5 us floor at GB300 HBM/LTS ceiling.

__global__ void vq_identity_copy_kernel(const float4* __restrict__ in,
                                        float4* __restrict__ out,
                                        int n4) {
    int i = blockIdx.x * blockDim.x + threadIdx.x;
    // grid-stride for safety if grid is clamped; normally one element per thread
    for (; i < n4; i += gridDim.x * blockDim.x) {
        out[i] = in[i];
    }
}

extern "C" void kernel_launch(void* const* d_in, const int* in_sizes, int n_in,
                              void* d_out, int out_size) {
    // d_in[0]: inputs  [32,32,32,64] float32  (in_sizes[0] = 2097152)
    // d_in[1]: embedding [1024,64]   float32  (unused in forward value)
    const float4* in = (const float4*)d_in[0];
    float4* out = (float4*)d_out;

    int n4 = out_size / 4;               // 2097152 / 4 = 524288 float4s
    const int block = 256;
    int grid = (n4 + block - 1) / block; // 2048 blocks

    vq_identity_copy_kernel<<<grid, block>>>(in, out, n4);
}